// round 1
// baseline (speedup 1.0000x reference)
#include <cuda_runtime.h>

#define N_SPK   1024
#define N_UTT   20
#define D_EMB   512
#define R_TOT   (N_SPK * N_UTT)      // 20480 rows
#define COS_EPS 1e-8f
#define SIM_EPS 1e-6f

// ---------------- scratch (device globals; no allocations allowed) ----------
__device__ float g_en[(size_t)R_TOT * D_EMB];   // normalized embeddings  (42 MB)
__device__ float g_cn[(size_t)N_SPK * D_EMB];   // normalized centroids   (2 MB)
__device__ float g_diag[R_TOT];                 // leave-one-out cosine
__device__ float g_diagc[R_TOT];                // e_n . c_n[same speaker]
__device__ float g_rowsum[R_TOT];               // sum_k exp(w*(cs+eps)+b)

// ---------------- fast exp on FMA pipe (avoids MUFU.EX2 throughput wall) ----
__device__ __forceinline__ float fexp(float x) {
    // valid for x in ~[-30, 10]; rel err ~2e-6
    float y = x * 1.4426950408889634f;      // x * log2(e)
    int   i = __float2int_rn(y);
    float f = y - (float)i;                 // |f| <= 0.5
    float t = f * 0.6931471805599453f;      // back to natural log domain, |t|<=0.347
    float p = fmaf(t, 0.008333333f, 0.041666667f);
    p = fmaf(t, p, 0.16666667f);
    p = fmaf(t, p, 0.5f);
    p = fmaf(t, p, 1.0f);
    p = fmaf(t, p, 1.0f);
    return __int_as_float((i + 127) << 23) * p;   // * 2^i
}

__device__ __forceinline__ float warpsum(float v) {
#pragma unroll
    for (int o = 16; o; o >>= 1) v += __shfl_down_sync(0xffffffffu, v, o);
    return v;
}

// ---------------- kernel A: per-speaker prep --------------------------------
// One block per speaker. Computes:
//   sums, normalized centroid c_n  -> g_cn
//   per-utterance normalized e_n   -> g_en
//   leave-one-out cosine           -> g_diag   (closed form, no cent_excl)
//   e_n . c_n (own speaker)        -> g_diagc
// Also zeroes g_rowsum for its 20 rows (so no memset node needed).
__global__ void __launch_bounds__(256) prep_kernel(const float* __restrict__ emb) {
    __shared__ float se[N_UTT * D_EMB];     // 40 KB
    __shared__ float sred[16];
    __shared__ float sbc[4];

    const int n   = blockIdx.x;
    const int tid = threadIdx.x;
    const int lane = tid & 31, wid = tid >> 5;

    // load this speaker's 20x512 block
    const float4* src = (const float4*)(emb + (size_t)n * N_UTT * D_EMB);
    float4* dst = (float4*)se;
#pragma unroll 4
    for (int i = tid; i < N_UTT * D_EMB / 4; i += 256) dst[i] = src[i];
    if (tid < N_UTT) g_rowsum[n * N_UTT + tid] = 0.0f;
    __syncthreads();

    const int d0 = tid, d1 = tid + 256;
    float s0 = 0.0f, s1 = 0.0f;
#pragma unroll
    for (int m = 0; m < N_UTT; m++) { s0 += se[m * D_EMB + d0]; s1 += se[m * D_EMB + d1]; }

    // S2 = ||sums||^2
    float p = s0 * s0 + s1 * s1;
    p = warpsum(p);
    if (lane == 0) sred[wid] = p;
    __syncthreads();
    if (tid == 0) {
        float S2 = 0.0f;
        for (int i = 0; i < 8; i++) S2 += sred[i];
        sbc[0] = S2;
        // c_n = (sums/M)/max(||sums||/M, eps) = sums/max(||sums||, M*eps)
        sbc[1] = 1.0f / fmaxf(sqrtf(S2), (float)N_UTT * COS_EPS);
    }
    __syncthreads();
    const float S2    = sbc[0];
    const float invcn = sbc[1];
    g_cn[(size_t)n * D_EMB + d0] = s0 * invcn;
    g_cn[(size_t)n * D_EMB + d1] = s1 * invcn;
    __syncthreads();

    for (int m = 0; m < N_UTT; m++) {
        const float e0 = se[m * D_EMB + d0], e1 = se[m * D_EMB + d1];
        float a = e0 * e0 + e1 * e1;      // partial ||e||^2
        float c = e0 * s0 + e1 * s1;      // partial e.sums
        a = warpsum(a); c = warpsum(c);
        if (lane == 0) { sred[wid] = a; sred[8 + wid] = c; }
        __syncthreads();
        if (tid == 0) {
            float en2 = 0.0f, des = 0.0f;
            for (int i = 0; i < 8; i++) { en2 += sred[i]; des += sred[8 + i]; }
            const float inve = 1.0f / fmaxf(sqrtf(en2), COS_EPS);
            // ||sums - e|| = sqrt(S2 - 2 des + en2)
            const float L = sqrtf(fmaxf(S2 - 2.0f * des + en2, 0.0f));
            g_diag[n * N_UTT + m]  = (des - en2) * inve / fmaxf(L, (float)(N_UTT - 1) * COS_EPS);
            g_diagc[n * N_UTT + m] = des * inve * invcn;
            sbc[2] = inve;
        }
        __syncthreads();
        const float inve = sbc[2];
        float* er = g_en + (size_t)(n * N_UTT + m) * D_EMB;
        er[d0] = e0 * inve;
        er[d1] = e1 * inve;
        __syncthreads();
    }
}

// ---------------- kernel B: GEMM + fused exp row-sum -------------------------
// cs[r, k] = e_n[r,:] . c_n[k,:]  (both K-major, A.B^T)
// epilogue: g_rowsum[r] += sum_k exp(w*(cs+eps)+b) over this tile's columns.
#define BM 64
#define BN 64
#define BK 32

__global__ void __launch_bounds__(256) gemm_expsum_kernel(const float* __restrict__ wp,
                                                          const float* __restrict__ bp) {
    __shared__ float As[BK][BM + 4];   // +4 pad: 16B-aligned float4 rows, reduced conflicts
    __shared__ float Bs[BK][BN + 4];

    const int tid  = threadIdx.x;
    const int col0 = blockIdx.x * BN;
    const int row0 = blockIdx.y * BM;
    const int ty = tid >> 4, tx = tid & 15;   // 16x16 thread grid, 4x4 per thread
    const int lr = tid >> 3, lc = tid & 7;    // loader: 32 rows x 8 float4

    float acc[4][4] = {};

    const float* Abase = g_en + (size_t)row0 * D_EMB;
    const float* Bbase = g_cn + (size_t)col0 * D_EMB;

    for (int kk = 0; kk < D_EMB; kk += BK) {
        const float4 a0 = *(const float4*)(Abase + (size_t)lr        * D_EMB + kk + lc * 4);
        const float4 a1 = *(const float4*)(Abase + (size_t)(lr + 32) * D_EMB + kk + lc * 4);
        const float4 b0 = *(const float4*)(Bbase + (size_t)lr        * D_EMB + kk + lc * 4);
        const float4 b1 = *(const float4*)(Bbase + (size_t)(lr + 32) * D_EMB + kk + lc * 4);
        __syncthreads();   // previous iter's compute done before overwrite
        As[lc * 4 + 0][lr] = a0.x; As[lc * 4 + 1][lr] = a0.y;
        As[lc * 4 + 2][lr] = a0.z; As[lc * 4 + 3][lr] = a0.w;
        As[lc * 4 + 0][lr + 32] = a1.x; As[lc * 4 + 1][lr + 32] = a1.y;
        As[lc * 4 + 2][lr + 32] = a1.z; As[lc * 4 + 3][lr + 32] = a1.w;
        Bs[lc * 4 + 0][lr] = b0.x; Bs[lc * 4 + 1][lr] = b0.y;
        Bs[lc * 4 + 2][lr] = b0.z; Bs[lc * 4 + 3][lr] = b0.w;
        Bs[lc * 4 + 0][lr + 32] = b1.x; Bs[lc * 4 + 1][lr + 32] = b1.y;
        Bs[lc * 4 + 2][lr + 32] = b1.z; Bs[lc * 4 + 3][lr + 32] = b1.w;
        __syncthreads();
#pragma unroll
        for (int k = 0; k < BK; k++) {
            const float4 av = *(const float4*)&As[k][ty * 4];
            const float4 bv = *(const float4*)&Bs[k][tx * 4];
            const float ar[4] = {av.x, av.y, av.z, av.w};
            const float br[4] = {bv.x, bv.y, bv.z, bv.w};
#pragma unroll
            for (int i = 0; i < 4; i++)
#pragma unroll
                for (int j = 0; j < 4; j++)
                    acc[i][j] = fmaf(ar[i], br[j], acc[i][j]);
        }
    }

    // epilogue: per-row partial exp-sum, reduce across the 16 column-threads
    const float w  = *wp;
    const float c0 = fmaf(w, SIM_EPS, *bp);   // b + w*eps
#pragma unroll
    for (int i = 0; i < 4; i++) {
        float s = 0.0f;
#pragma unroll
        for (int j = 0; j < 4; j++) s += fexp(fmaf(w, acc[i][j], c0));
#pragma unroll
        for (int o = 8; o; o >>= 1) s += __shfl_down_sync(0xffffffffu, s, o, 16);
        if (tx == 0) atomicAdd(&g_rowsum[row0 + ty * 4 + i], s);
    }
}

// ---------------- kernel C: diagonal fixup + LSE + final reduce --------------
__global__ void __launch_bounds__(1024) finalize_kernel(const float* __restrict__ wp,
                                                        const float* __restrict__ bp,
                                                        float* __restrict__ out) {
    __shared__ float sred[32];
    const int tid = threadIdx.x;
    const float w  = *wp;
    const float c0 = fmaf(w, SIM_EPS, *bp);
    float acc = 0.0f;
#pragma unroll
    for (int r = tid; r < R_TOT; r += 1024) {
        const float pos = fmaf(w, g_diag[r], c0);              // w*(diag+eps)+b
        // swap same-speaker column: remove exp(vs full centroid), add exp(leave-one-out)
        const float s = g_rowsum[r] - fexp(fmaf(w, g_diagc[r], c0)) + fexp(pos) + SIM_EPS;
        acc += logf(s) - pos;
    }
    acc = warpsum(acc);
    if ((tid & 31) == 0) sred[tid >> 5] = acc;
    __syncthreads();
    if (tid < 32) {
        float v = sred[tid];
        v = warpsum(v);
        if (tid == 0) out[0] = v;
    }
}

// ---------------- launch -----------------------------------------------------
extern "C" void kernel_launch(void* const* d_in, const int* in_sizes, int n_in,
                              void* d_out, int out_size) {
    const float* emb = (const float*)d_in[0];
    const float* w   = (const float*)d_in[1];
    const float* b   = (const float*)d_in[2];

    prep_kernel<<<N_SPK, 256>>>(emb);
    gemm_expsum_kernel<<<dim3(N_SPK / BN, R_TOT / BM), 256>>>(w, b);
    finalize_kernel<<<1, 1024>>>(w, b, (float*)d_out);
}

// round 5
// speedup vs baseline: 5.2494x; 5.2494x over previous
#include <cuda_runtime.h>
#include <cuda_bf16.h>
#include <cstdint>

#define N_SPK   1024
#define N_UTT   20
#define D_EMB   512
#define R_TOT   (N_SPK * N_UTT)      // 20480 rows
#define COS_EPS 1e-8f
#define SIM_EPS 1e-6f

// ---------------- scratch (device globals; no allocations allowed) ----------
__device__ uint4 g_en_bf[(size_t)R_TOT * D_EMB * 2 / 16];   // 21 MB bf16 row-major
__device__ uint4 g_cn_bf[(size_t)N_SPK * D_EMB * 2 / 16];   //  1 MB bf16 row-major
__device__ float g_diag[R_TOT];                 // leave-one-out cosine (fp32 exact)
__device__ float g_diagc[R_TOT];                // e_n . c_n[same speaker] (fp32 exact)
__device__ float g_rowsum[R_TOT];               // sum_k exp(w*(cs+eps)+b)

// ---------------- PTX helpers ------------------------------------------------
__device__ __forceinline__ uint32_t smem_u32(const void* p) {
    uint32_t a;
    asm("{ .reg .u64 t; cvta.to.shared.u64 t, %1; cvt.u32.u64 %0, t; }" : "=r"(a) : "l"(p));
    return a;
}
#define CP_ASYNC16(dst, src) \
    asm volatile("cp.async.cg.shared.global [%0], [%1], 16;" :: "r"(dst), "l"(src) : "memory")
#define CP_COMMIT() asm volatile("cp.async.commit_group;" ::: "memory")
#define CP_WAIT1()  asm volatile("cp.async.wait_group 1;" ::: "memory")
#define CP_WAIT0()  asm volatile("cp.async.wait_group 0;" ::: "memory")
#define LDSM_X4(r0, r1, r2, r3, a) \
    asm volatile("ldmatrix.sync.aligned.m8n8.x4.shared.b16 {%0,%1,%2,%3}, [%4];" \
                 : "=r"(r0), "=r"(r1), "=r"(r2), "=r"(r3) : "r"(a))
__device__ __forceinline__ void mma_bf16(float* c, const uint32_t* a, const uint32_t* b) {
    asm volatile(
        "mma.sync.aligned.m16n8k16.row.col.f32.bf16.bf16.f32 "
        "{%0,%1,%2,%3}, {%4,%5,%6,%7}, {%8,%9}, {%0,%1,%2,%3};"
        : "+f"(c[0]), "+f"(c[1]), "+f"(c[2]), "+f"(c[3])
        : "r"(a[0]), "r"(a[1]), "r"(a[2]), "r"(a[3]), "r"(b[0]), "r"(b[1]));
}

// ---------------- fast exp on FMA pipe ---------------------------------------
__device__ __forceinline__ float fexp(float x) {
    float y = x * 1.4426950408889634f;
    int   i = __float2int_rn(y);
    float f = y - (float)i;
    float t = f * 0.6931471805599453f;
    float p = fmaf(t, 0.008333333f, 0.041666667f);
    p = fmaf(t, p, 0.16666667f);
    p = fmaf(t, p, 0.5f);
    p = fmaf(t, p, 1.0f);
    p = fmaf(t, p, 1.0f);
    return __int_as_float((i + 127) << 23) * p;
}

__device__ __forceinline__ float warpsum(float v) {
#pragma unroll
    for (int o = 16; o; o >>= 1) v += __shfl_down_sync(0xffffffffu, v, o);
    return v;
}

// ---------------- kernel A: per-speaker prep (bf16 outputs) ------------------
__global__ void __launch_bounds__(256) prep_kernel(const float* __restrict__ emb) {
    __shared__ float se[N_UTT * D_EMB];     // 40 KB
    __shared__ float sred[16];
    __shared__ float sbc[4];

    const int n   = blockIdx.x;
    const int tid = threadIdx.x;
    const int lane = tid & 31, wid = tid >> 5;

    const float4* src = (const float4*)(emb + (size_t)n * N_UTT * D_EMB);
    float4* dst = (float4*)se;
#pragma unroll 4
    for (int i = tid; i < N_UTT * D_EMB / 4; i += 256) dst[i] = src[i];
    if (tid < N_UTT) g_rowsum[n * N_UTT + tid] = 0.0f;
    __syncthreads();

    const int d0 = tid, d1 = tid + 256;
    float s0 = 0.0f, s1 = 0.0f;
#pragma unroll
    for (int m = 0; m < N_UTT; m++) { s0 += se[m * D_EMB + d0]; s1 += se[m * D_EMB + d1]; }

    float p = s0 * s0 + s1 * s1;
    p = warpsum(p);
    if (lane == 0) sred[wid] = p;
    __syncthreads();
    if (tid == 0) {
        float S2 = 0.0f;
        for (int i = 0; i < 8; i++) S2 += sred[i];
        sbc[0] = S2;
        sbc[1] = 1.0f / fmaxf(sqrtf(S2), (float)N_UTT * COS_EPS);
    }
    __syncthreads();
    const float S2    = sbc[0];
    const float invcn = sbc[1];
    __nv_bfloat16* cnb = (__nv_bfloat16*)g_cn_bf + (size_t)n * D_EMB;
    cnb[d0] = __float2bfloat16(s0 * invcn);
    cnb[d1] = __float2bfloat16(s1 * invcn);
    __syncthreads();

    for (int m = 0; m < N_UTT; m++) {
        const float e0 = se[m * D_EMB + d0], e1 = se[m * D_EMB + d1];
        float a = e0 * e0 + e1 * e1;      // partial ||e||^2
        float c = e0 * s0 + e1 * s1;      // partial e.sums
        a = warpsum(a); c = warpsum(c);
        if (lane == 0) { sred[wid] = a; sred[8 + wid] = c; }
        __syncthreads();
        if (tid == 0) {
            float en2 = 0.0f, des = 0.0f;
            for (int i = 0; i < 8; i++) { en2 += sred[i]; des += sred[8 + i]; }
            const float inve = 1.0f / fmaxf(sqrtf(en2), COS_EPS);
            const float L = sqrtf(fmaxf(S2 - 2.0f * des + en2, 0.0f));
            g_diag[n * N_UTT + m]  = (des - en2) * inve / fmaxf(L, (float)(N_UTT - 1) * COS_EPS);
            g_diagc[n * N_UTT + m] = des * inve * invcn;
            sbc[2] = inve;
        }
        __syncthreads();
        const float inve = sbc[2];
        __nv_bfloat16* er = (__nv_bfloat16*)g_en_bf + (size_t)(n * N_UTT + m) * D_EMB;
        er[d0] = __float2bfloat16(e0 * inve);
        er[d1] = __float2bfloat16(e1 * inve);
        __syncthreads();
    }
}

// ---------------- kernel B: HMMA bf16 GEMM + fused exp row-sum ---------------
// C[20480,1024] = A_bf16 . B_bf16^T, both K-major, K=512.
// CTA 128x128, BK=32 (16 chunks), cp.async double buffer, 8 warps (4x2),
// warp tile 32x64 via m16n8k16 HMMA.
#define SROW 80                       // padded smem row stride in bytes (64B data)

__global__ void __launch_bounds__(256) gemm_expsum_kernel(const float* __restrict__ wp,
                                                          const float* __restrict__ bp) {
    __shared__ __align__(16) char smA[2][128 * SROW];   // 20 KB
    __shared__ __align__(16) char smB[2][128 * SROW];   // 20 KB

    const int tid  = threadIdx.x;
    const int wid  = tid >> 5, lane = tid & 31;
    const int row0 = blockIdx.y * 128;
    const int col0 = blockIdx.x * 128;
    const int wr   = wid >> 1;        // warp row 0..3 (32 rows each)
    const int wc   = wid & 1;         // warp col 0..1 (64 cols each)

    const char* Ag = (const char*)g_en_bf + (size_t)row0 * (D_EMB * 2);
    const char* Bg = (const char*)g_cn_bf + (size_t)col0 * (D_EMB * 2);

    const uint32_t sA = smem_u32(smA);
    const uint32_t sB = smem_u32(smB);

    float acc[2][8][4] = {};

#define PREFETCH(c)                                                              \
    do {                                                                         \
        const int _buf = (c) & 1;                                                \
        _Pragma("unroll")                                                        \
        for (int _p = 0; _p < 2; _p++) {                                         \
            const int _i   = tid + _p * 256;                                     \
            const int _r   = _i >> 2;                                            \
            const int _c16 = _i & 3;                                             \
            CP_ASYNC16(sA + _buf * 128 * SROW + _r * SROW + _c16 * 16,           \
                       Ag + (size_t)_r * 1024 + (c) * 64 + _c16 * 16);           \
            CP_ASYNC16(sB + _buf * 128 * SROW + _r * SROW + _c16 * 16,           \
                       Bg + (size_t)_r * 1024 + (c) * 64 + _c16 * 16);           \
        }                                                                        \
        CP_COMMIT();                                                             \
    } while (0)

    PREFETCH(0);

    const int lm = lane & 15;          // ldmatrix row within 16-row block
    const int lh = lane >> 4;          // 0/1 -> k-halves

    for (int c = 0; c < 16; c++) {
        if (c < 15) { PREFETCH(c + 1); CP_WAIT1(); }
        else        { CP_WAIT0(); }
        __syncthreads();

        const int buf = c & 1;
        const uint32_t ab = sA + buf * 128 * SROW;
        const uint32_t bb = sB + buf * 128 * SROW;

#pragma unroll
        for (int k16 = 0; k16 < 2; k16++) {
            const uint32_t koff = k16 * 32 + lh * 16;
            uint32_t afr[2][4], bfr[4][4];
#pragma unroll
            for (int mb = 0; mb < 2; mb++)
                LDSM_X4(afr[mb][0], afr[mb][1], afr[mb][2], afr[mb][3],
                        ab + (wr * 32 + mb * 16 + lm) * SROW + koff);
#pragma unroll
            for (int j2 = 0; j2 < 4; j2++)
                LDSM_X4(bfr[j2][0], bfr[j2][1], bfr[j2][2], bfr[j2][3],
                        bb + (wc * 64 + j2 * 16 + lm) * SROW + koff);
#pragma unroll
            for (int mb = 0; mb < 2; mb++)
#pragma unroll
                for (int j = 0; j < 8; j++) {
                    uint32_t brg[2];
                    brg[0] = bfr[j >> 1][(j & 1)];
                    brg[1] = bfr[j >> 1][(j & 1) + 2];
                    mma_bf16(acc[mb][j], afr[mb], brg);
                }
        }
        __syncthreads();
    }

    // ---- fused epilogue: per-row sum of exp(w*(cs+eps)+b) over 128 cols ----
    const float w  = *wp;
    const float c0 = fmaf(w, SIM_EPS, *bp);
#pragma unroll
    for (int mb = 0; mb < 2; mb++) {
        float s0 = 0.0f, s1 = 0.0f;
#pragma unroll
        for (int j = 0; j < 8; j++) {
            s0 += fexp(fmaf(w, acc[mb][j][0], c0)) + fexp(fmaf(w, acc[mb][j][1], c0));
            s1 += fexp(fmaf(w, acc[mb][j][2], c0)) + fexp(fmaf(w, acc[mb][j][3], c0));
        }
        s0 += __shfl_xor_sync(0xffffffffu, s0, 1);
        s0 += __shfl_xor_sync(0xffffffffu, s0, 2);
        s1 += __shfl_xor_sync(0xffffffffu, s1, 1);
        s1 += __shfl_xor_sync(0xffffffffu, s1, 2);
        if ((lane & 3) == 0) {
            const int r = row0 + wr * 32 + mb * 16 + (lane >> 2);
            atomicAdd(&g_rowsum[r],     s0);
            atomicAdd(&g_rowsum[r + 8], s1);
        }
    }
#undef PREFETCH
}

// ---------------- kernel C: diagonal fixup + LSE + final reduce --------------
__global__ void __launch_bounds__(1024) finalize_kernel(const float* __restrict__ wp,
                                                        const float* __restrict__ bp,
                                                        float* __restrict__ out) {
    __shared__ float sred[32];
    const int tid = threadIdx.x;
    const float w  = *wp;
    const float c0 = fmaf(w, SIM_EPS, *bp);
    float acc = 0.0f;
#pragma unroll
    for (int r = tid; r < R_TOT; r += 1024) {
        const float pos = fmaf(w, g_diag[r], c0);
        const float s = g_rowsum[r] - fexp(fmaf(w, g_diagc[r], c0)) + fexp(pos) + SIM_EPS;
        acc += logf(s) - pos;
    }
    acc = warpsum(acc);
    if ((tid & 31) == 0) sred[tid >> 5] = acc;
    __syncthreads();
    if (tid < 32) {
        float v = sred[tid];
        v = warpsum(v);
        if (tid == 0) out[0] = v;
    }
}

// ---------------- launch -----------------------------------------------------
extern "C" void kernel_launch(void* const* d_in, const int* in_sizes, int n_in,
                              void* d_out, int out_size) {
    const float* emb = (const float*)d_in[0];
    const float* w   = (const float*)d_in[1];
    const float* b   = (const float*)d_in[2];

    prep_kernel<<<N_SPK, 256>>>(emb);
    gemm_expsum_kernel<<<dim3(N_SPK / 128, R_TOT / 128), 256>>>(w, b);
    finalize_kernel<<<1, 1024>>>(w, b, (float*)d_out);
}

// round 6
// speedup vs baseline: 6.9432x; 1.3227x over previous
#include <cuda_runtime.h>
#include <cuda_bf16.h>
#include <cstdint>

#define N_SPK   1024
#define N_UTT   20
#define D_EMB   512
#define R_TOT   (N_SPK * N_UTT)      // 20480 rows
#define COS_EPS 1e-8f
#define SIM_EPS 1e-6f

// ---------------- scratch (device globals; no allocations allowed) ----------
__device__ uint4 g_en_bf[(size_t)R_TOT * D_EMB * 2 / 16];   // 21 MB bf16 row-major
__device__ uint4 g_cn_bf[(size_t)N_SPK * D_EMB * 2 / 16];   //  1 MB bf16 row-major
__device__ float g_diag[R_TOT];                 // leave-one-out cosine (fp32 exact)
__device__ float g_diagc[R_TOT];                // e_n . c_n[same speaker] (fp32 exact)
__device__ float g_rowsum[R_TOT];               // sum_k exp(w*(cs+eps)+b)

// ---------------- PTX helpers ------------------------------------------------
__device__ __forceinline__ uint32_t smem_u32(const void* p) {
    uint32_t a;
    asm("{ .reg .u64 t; cvta.to.shared.u64 t, %1; cvt.u32.u64 %0, t; }" : "=r"(a) : "l"(p));
    return a;
}
#define CP_ASYNC16(dst, src) \
    asm volatile("cp.async.cg.shared.global [%0], [%1], 16;" :: "r"(dst), "l"(src) : "memory")
#define CP_COMMIT() asm volatile("cp.async.commit_group;" ::: "memory")
#define CP_WAIT1()  asm volatile("cp.async.wait_group 1;" ::: "memory")
#define CP_WAIT0()  asm volatile("cp.async.wait_group 0;" ::: "memory")
#define LDSM_X4(r0, r1, r2, r3, a) \
    asm volatile("ldmatrix.sync.aligned.m8n8.x4.shared.b16 {%0,%1,%2,%3}, [%4];" \
                 : "=r"(r0), "=r"(r1), "=r"(r2), "=r"(r3) : "r"(a))
__device__ __forceinline__ void mma_bf16(float* c, const uint32_t* a, const uint32_t* b) {
    asm volatile(
        "mma.sync.aligned.m16n8k16.row.col.f32.bf16.bf16.f32 "
        "{%0,%1,%2,%3}, {%4,%5,%6,%7}, {%8,%9}, {%0,%1,%2,%3};"
        : "+f"(c[0]), "+f"(c[1]), "+f"(c[2]), "+f"(c[3])
        : "r"(a[0]), "r"(a[1]), "r"(a[2]), "r"(a[3]), "r"(b[0]), "r"(b[1]));
}

// ---------------- fast exp on FMA pipe ---------------------------------------
__device__ __forceinline__ float fexp(float x) {
    float y = x * 1.4426950408889634f;
    int   i = __float2int_rn(y);
    float f = y - (float)i;
    float t = f * 0.6931471805599453f;
    float p = fmaf(t, 0.008333333f, 0.041666667f);
    p = fmaf(t, p, 0.16666667f);
    p = fmaf(t, p, 0.5f);
    p = fmaf(t, p, 1.0f);
    p = fmaf(t, p, 1.0f);
    return __int_as_float((i + 127) << 23) * p;
}

__device__ __forceinline__ float warpsum(float v) {
#pragma unroll
    for (int o = 16; o; o >>= 1) v += __shfl_down_sync(0xffffffffu, v, o);
    return v;
}

// ---------------- kernel A: per-speaker prep (register-resident) -------------
// One block (256 thr) per speaker. Thread owns dim pair (2*tid, 2*tid+1);
// all 20 utterance values live in registers. sums needs no reduction; the 20
// (||e||^2, e.sums) pairs are warpsum'd unrolled + one cross-warp pass.
__global__ void __launch_bounds__(256) prep_kernel(const float* __restrict__ emb) {
    __shared__ float sp[8][2 * N_UTT];   // per-warp partials (en2, des)
    __shared__ float sred2[8];           // per-warp ||sums||^2 partials
    __shared__ float sbc[N_UTT + 2];     // inve[20], invcn

    const int n = blockIdx.x, tid = threadIdx.x;
    const int lane = tid & 31, wid = tid >> 5;
    const float2* base = (const float2*)(emb + (size_t)n * (N_UTT * D_EMB)) + tid;

    float2 e[N_UTT];
    float sx = 0.0f, sy = 0.0f;
#pragma unroll
    for (int m = 0; m < N_UTT; m++) {
        e[m] = base[m * (D_EMB / 2)];
        sx += e[m].x; sy += e[m].y;
    }
    if (tid < N_UTT) g_rowsum[n * N_UTT + tid] = 0.0f;

    float p = sx * sx + sy * sy;
    p = warpsum(p);
    if (lane == 0) sred2[wid] = p;

#pragma unroll
    for (int m = 0; m < N_UTT; m++) {
        float a = e[m].x * e[m].x + e[m].y * e[m].y;   // partial ||e||^2
        float c = e[m].x * sx + e[m].y * sy;           // partial e.sums
        a = warpsum(a); c = warpsum(c);
        if (lane == 0) { sp[wid][m] = a; sp[wid][N_UTT + m] = c; }
    }
    __syncthreads();

    if (tid < N_UTT) {
        float en2 = 0.0f, des = 0.0f, S2 = 0.0f;
#pragma unroll
        for (int w2 = 0; w2 < 8; w2++) {
            en2 += sp[w2][tid]; des += sp[w2][N_UTT + tid]; S2 += sred2[w2];
        }
        const float inve  = 1.0f / fmaxf(sqrtf(en2), COS_EPS);
        const float invcn = 1.0f / fmaxf(sqrtf(S2), (float)N_UTT * COS_EPS);
        const float L = sqrtf(fmaxf(S2 - 2.0f * des + en2, 0.0f));
        g_diag[n * N_UTT + tid]  = (des - en2) * inve / fmaxf(L, (float)(N_UTT - 1) * COS_EPS);
        g_diagc[n * N_UTT + tid] = des * inve * invcn;
        sbc[tid] = inve;
        if (tid == 0) sbc[N_UTT] = invcn;
    }
    __syncthreads();

    const float invcn = sbc[N_UTT];
    __nv_bfloat162* cnb = (__nv_bfloat162*)((__nv_bfloat16*)g_cn_bf + (size_t)n * D_EMB) + tid;
    *cnb = __floats2bfloat162_rn(sx * invcn, sy * invcn);
#pragma unroll
    for (int m = 0; m < N_UTT; m++) {
        const float inve = sbc[m];
        __nv_bfloat162* er = (__nv_bfloat162*)((__nv_bfloat16*)g_en_bf +
                             (size_t)(n * N_UTT + m) * D_EMB) + tid;
        *er = __floats2bfloat162_rn(e[m].x * inve, e[m].y * inve);
    }
}

// ---------------- kernel B: HMMA bf16 GEMM + fused exp row-sum ---------------
// C[20480,1024] = A_bf16 . B_bf16^T, both K-major, K=512.
// CTA 128x128, BK=64 (8 chunks), 3-stage cp.async pipeline, XOR-128B swizzle,
// 8 warps (4x2), warp tile 32x64 via m16n8k16 HMMA.
#define STAGE_BYTES 32768                 // A 16KB + B 16KB per stage (128 rows x 128B)
#define GSMEM (3 * STAGE_BYTES)           // 96 KB dynamic

__global__ void __launch_bounds__(256, 2) gemm_expsum_kernel(const float* __restrict__ wp,
                                                             const float* __restrict__ bp) {
    extern __shared__ __align__(16) char smem[];
    const uint32_t sb = smem_u32(smem);

    const int tid  = threadIdx.x;
    const int wid  = tid >> 5, lane = tid & 31;
    const int row0 = blockIdx.y * 128;
    const int col0 = blockIdx.x * 128;
    const int wr   = wid >> 1;        // warp row 0..3 (32 rows each)
    const int wc   = wid & 1;         // warp col 0..1 (64 cols each)

    const char* Ag = (const char*)g_en_bf + (size_t)row0 * (D_EMB * 2);
    const char* Bg = (const char*)g_cn_bf + (size_t)col0 * (D_EMB * 2);

    float acc[2][8][4] = {};

    // per-thread loader coords: 4 x 16B per operand per chunk
    const int l_row[4] = { (tid + 0) >> 3, (tid + 256) >> 3, (tid + 512) >> 3, (tid + 768) >> 3 };
    const int l_c16 = tid & 7;

#define PREFETCH(c)                                                              \
    do {                                                                         \
        const uint32_t _st = sb + ((c) % 3) * STAGE_BYTES;                       \
        _Pragma("unroll")                                                        \
        for (int _p = 0; _p < 4; _p++) {                                         \
            const int _r = l_row[_p];                                            \
            const uint32_t _off = (uint32_t)_r * 128 + l_c16 * 16;               \
            const uint32_t _sw  = _off ^ ((_off >> 3) & 0x70);                   \
            CP_ASYNC16(_st + _sw,         Ag + (size_t)_r * 1024 + (c) * 128 + l_c16 * 16); \
            CP_ASYNC16(_st + 16384 + _sw, Bg + (size_t)_r * 1024 + (c) * 128 + l_c16 * 16); \
        }                                                                        \
        CP_COMMIT();                                                             \
    } while (0)

    PREFETCH(0);
    PREFETCH(1);

    const int lm = lane & 15;          // ldmatrix row within 16-row block
    const int lh = lane >> 4;          // 0/1 -> 16B k-half

    for (int c = 0; c < 8; c++) {
        if (c < 7) CP_WAIT1(); else CP_WAIT0();
        __syncthreads();               // stage c ready; everyone done with c-1
        if (c < 6) PREFETCH(c + 2);    // overwrites stage (c-1)%3 — safe now

        const uint32_t ab = sb + (c % 3) * STAGE_BYTES;
        const uint32_t bb = ab + 16384;

#pragma unroll
        for (int k16 = 0; k16 < 4; k16++) {
            const uint32_t koff = k16 * 32 + lh * 16;
            uint32_t afr[2][4], bfr[4][4];
#pragma unroll
            for (int mb = 0; mb < 2; mb++) {
                const uint32_t off = (uint32_t)(wr * 32 + mb * 16 + lm) * 128 + koff;
                LDSM_X4(afr[mb][0], afr[mb][1], afr[mb][2], afr[mb][3],
                        ab + (off ^ ((off >> 3) & 0x70)));
            }
#pragma unroll
            for (int j2 = 0; j2 < 4; j2++) {
                const uint32_t off = (uint32_t)(wc * 64 + j2 * 16 + lm) * 128 + koff;
                LDSM_X4(bfr[j2][0], bfr[j2][1], bfr[j2][2], bfr[j2][3],
                        bb + (off ^ ((off >> 3) & 0x70)));
            }
#pragma unroll
            for (int mb = 0; mb < 2; mb++)
#pragma unroll
                for (int j = 0; j < 8; j++) {
                    uint32_t brg[2];
                    brg[0] = bfr[j >> 1][(j & 1)];
                    brg[1] = bfr[j >> 1][(j & 1) + 2];
                    mma_bf16(acc[mb][j], afr[mb], brg);
                }
        }
    }

    // ---- fused epilogue: per-row sum of exp(w*(cs+eps)+b) over 128 cols ----
    const float w  = *wp;
    const float c0 = fmaf(w, SIM_EPS, *bp);
#pragma unroll
    for (int mb = 0; mb < 2; mb++) {
        float s0 = 0.0f, s1 = 0.0f;
#pragma unroll
        for (int j = 0; j < 8; j++) {
            s0 += fexp(fmaf(w, acc[mb][j][0], c0)) + fexp(fmaf(w, acc[mb][j][1], c0));
            s1 += fexp(fmaf(w, acc[mb][j][2], c0)) + fexp(fmaf(w, acc[mb][j][3], c0));
        }
        s0 += __shfl_xor_sync(0xffffffffu, s0, 1);
        s0 += __shfl_xor_sync(0xffffffffu, s0, 2);
        s1 += __shfl_xor_sync(0xffffffffu, s1, 1);
        s1 += __shfl_xor_sync(0xffffffffu, s1, 2);
        if ((lane & 3) == 0) {
            const int r = row0 + wr * 32 + mb * 16 + (lane >> 2);
            atomicAdd(&g_rowsum[r],     s0);
            atomicAdd(&g_rowsum[r + 8], s1);
        }
    }
#undef PREFETCH
}

// ---------------- kernel C: diagonal fixup + LSE + final reduce --------------
__global__ void __launch_bounds__(1024) finalize_kernel(const float* __restrict__ wp,
                                                        const float* __restrict__ bp,
                                                        float* __restrict__ out) {
    __shared__ float sred[32];
    const int tid = threadIdx.x;
    const float w  = *wp;
    const float c0 = fmaf(w, SIM_EPS, *bp);
    float acc = 0.0f;
#pragma unroll
    for (int r = tid; r < R_TOT; r += 1024) {
        const float pos = fmaf(w, g_diag[r], c0);
        const float s = g_rowsum[r] - fexp(fmaf(w, g_diagc[r], c0)) + fexp(pos) + SIM_EPS;
        acc += logf(s) - pos;
    }
    acc = warpsum(acc);
    if ((tid & 31) == 0) sred[tid >> 5] = acc;
    __syncthreads();
    if (tid < 32) {
        float v = sred[tid];
        v = warpsum(v);
        if (tid == 0) out[0] = v;
    }
}

// ---------------- launch -----------------------------------------------------
extern "C" void kernel_launch(void* const* d_in, const int* in_sizes, int n_in,
                              void* d_out, int out_size) {
    const float* emb = (const float*)d_in[0];
    const float* w   = (const float*)d_in[1];
    const float* b   = (const float*)d_in[2];

    cudaFuncSetAttribute(gemm_expsum_kernel,
                         cudaFuncAttributeMaxDynamicSharedMemorySize, GSMEM);

    prep_kernel<<<N_SPK, 256>>>(emb);
    gemm_expsum_kernel<<<dim3(N_SPK / 128, R_TOT / 128), 256, GSMEM>>>(w, b);
    finalize_kernel<<<1, 1024>>>(w, b, (float*)d_out);
}